// round 2
// baseline (speedup 1.0000x reference)
#include <cuda_runtime.h>

// Problem constants
#define NN      64
#define C_TOT   64
#define WIN     4096
#define FF      64
#define KW      9
#define OW      4088          // WIN - KW + 1
#define T_TILE  128
#define CHUNK   16            // channels per shared-memory chunk
#define XROW    (T_TILE + 8)  // 136 floats per staged x row

// ---------- packed fp32x2 helpers (Blackwell-only; ptxas will not auto-fuse) ----------
__device__ __forceinline__ unsigned long long pk2(float lo, float hi) {
    unsigned long long r;
    asm("mov.b64 %0, {%1, %2};" : "=l"(r) : "f"(lo), "f"(hi));
    return r;
}
__device__ __forceinline__ unsigned long long ffma2(unsigned long long a,
                                                    unsigned long long b,
                                                    unsigned long long c) {
    unsigned long long d;
    asm("fma.rn.f32x2 %0, %1, %2, %3;" : "=l"(d) : "l"(a), "l"(b), "l"(c));
    return d;
}
__device__ __forceinline__ float2 upk2(unsigned long long v) {
    float2 f;
    asm("mov.b64 {%0, %1}, %2;" : "=f"(f.x), "=f"(f.y) : "l"(v));
    return f;
}

__global__ __launch_bounds__(256, 2)
void conv1d_f32x2_kernel(const float* __restrict__ x,
                         const float* __restrict__ filt,
                         const float* __restrict__ bias,
                         float* __restrict__ out)
{
    __shared__ float x_s[CHUNK][XROW];        // 8704 B
    __shared__ float f_s[CHUNK][FF][KW];      // 36864 B  (total 45568 B < 48 KB)

    const int tid   = threadIdx.x;
    const int tg    = tid & 7;        // 8 t-groups of 16 outputs
    const int fpair = tid >> 3;       // 32 filter pairs
    const int n     = blockIdx.y;
    const int t0    = blockIdx.x * T_TILE;
    const int tbase = t0 + tg * 16;

    unsigned long long acc[2][8];
    #pragma unroll
    for (int a = 0; a < 2; a++)
        #pragma unroll
        for (int j = 0; j < 8; j++) acc[a][j] = 0ULL;

    const bool full = (t0 + XROW) <= WIN;   // only the last t-tile needs guarding

    for (int chunk = 0; chunk < 4; ++chunk) {
        const int c0 = chunk * CHUNK;
        if (chunk) __syncthreads();

        // ---- stage x chunk: [CHUNK][XROW] ----
        if (full) {
            #pragma unroll
            for (int i = tid; i < CHUNK * 34; i += 256) {   // 34 float4 per row
                int row = i / 34, c4 = i - row * 34;
                const float4 v = *reinterpret_cast<const float4*>(
                    x + ((size_t)n * C_TOT + c0 + row) * WIN + t0 + c4 * 4);
                *reinterpret_cast<float4*>(&x_s[row][c4 * 4]) = v;
            }
        } else {
            for (int i = tid; i < CHUNK * XROW; i += 256) {
                int row = i / XROW, col = i - row * XROW;
                int t = t0 + col;
                x_s[row][col] = (t < WIN)
                    ? x[((size_t)n * C_TOT + c0 + row) * WIN + t] : 0.0f;
            }
        }

        // ---- stage filter chunk: f_s[cc][f][w] ----
        // filt[f][c0+cc][w] -> 144 contiguous floats per f: fully coalesced
        for (int i = tid; i < CHUNK * FF * KW; i += 256) {
            int f = i / (CHUNK * KW);
            int r = i - f * (CHUNK * KW);
            int cc = r / KW, w = r - cc * KW;
            f_s[cc][f][w] = filt[f * (C_TOT * KW) + c0 * KW + r];
        }
        __syncthreads();

        // ---- compute: 16 channels, 9-tap FIR on f32x2 pairs ----
        #pragma unroll 1
        for (int cc = 0; cc < CHUNK; ++cc) {
            float xw[24];
            const float4* xs4 = reinterpret_cast<const float4*>(&x_s[cc][tg * 16]);
            #pragma unroll
            for (int v = 0; v < 6; v++) {
                float4 q = xs4[v];
                xw[v*4+0] = q.x; xw[v*4+1] = q.y; xw[v*4+2] = q.z; xw[v*4+3] = q.w;
            }
            // even-aligned pairs A[j]=(x[2j],x[2j+1]) and odd-aligned B[j]=(x[2j+1],x[2j+2])
            unsigned long long A[12], B[11];
            #pragma unroll
            for (int j = 0; j < 12; j++) A[j] = pk2(xw[2*j],   xw[2*j+1]);
            #pragma unroll
            for (int j = 0; j < 11; j++) B[j] = pk2(xw[2*j+1], xw[2*j+2]);

            #pragma unroll
            for (int ff = 0; ff < 2; ++ff) {
                const int f = fpair * 2 + ff;
                #pragma unroll
                for (int w = 0; w < KW; ++w) {
                    const float fv = f_s[cc][f][w];
                    const unsigned long long wp = pk2(fv, fv);
                    if ((w & 1) == 0) {
                        #pragma unroll
                        for (int j = 0; j < 8; j++)
                            acc[ff][j] = ffma2(A[j + (w >> 1)], wp, acc[ff][j]);
                    } else {
                        #pragma unroll
                        for (int j = 0; j < 8; j++)
                            acc[ff][j] = ffma2(B[j + (w >> 1)], wp, acc[ff][j]);
                    }
                }
            }
        }
    }

    // ---- epilogue: + C*bias[f], aligned float2 stores ----
    #pragma unroll
    for (int ff = 0; ff < 2; ++ff) {
        const int f = fpair * 2 + ff;
        const float bb = 64.0f * bias[f];
        float* orow = out + ((size_t)n * FF + f) * OW;
        #pragma unroll
        for (int j = 0; j < 8; j++) {
            int t = tbase + 2 * j;
            if (t < OW) {                       // OW even: a pair never straddles
                float2 v = upk2(acc[ff][j]);
                v.x += bb; v.y += bb;
                *reinterpret_cast<float2*>(orow + t) = v;
            }
        }
    }
}

extern "C" void kernel_launch(void* const* d_in, const int* in_sizes, int n_in,
                              void* d_out, int out_size) {
    const float* x    = (const float*)d_in[0];   // [64,64,4096]
    const float* filt = (const float*)d_in[1];   // [64,64,9]
    const float* bias = (const float*)d_in[2];   // [64]
    float* out = (float*)d_out;                  // [64,64,4088]

    dim3 grid((OW + T_TILE - 1) / T_TILE, NN);   // (32, 64)
    conv1d_f32x2_kernel<<<grid, 256>>>(x, filt, bias, out);
}